// round 16
// baseline (speedup 1.0000x reference)
#include <cuda_runtime.h>
#include <cuda_bf16.h>
#include <cuda_fp16.h>
#include <cuda_fp8.h>
#include <cstdint>
#include <stdint.h>
#include <math.h>

// NTXent loss, t = 0.5 — FP8 e4m3 mma, f16 accum, occupancy-focused rewrite.
// R15 finding: gemm was latency-bound (1 mma / 38 cyc / SMSP), not FLOP-bound.
// Fix: 8 warps/CTA with 32x64 warp tiles (32 accum regs) + streaming epilogue
// (no e[][] array) -> ~90 regs -> 2+ CTAs/SM -> 4+ warps/SMSP overlap.
//
// K1: normalize h1/h2 rows -> e4m3 H8[16384][128], fp32 pos dots, zero rowsums
// K2: one CTA per upper-triangular 128x128 tile of S = H H^T.
//     mma.sync.m16n8k32.f16.e4m3.e4m3.f16. Epilogue: exp(2s) via ex2 streamed
//     into row sums (bi rows) and column sums (bj rows, symmetry).
// K3: final log + mean reduction.

#define NROWS 16384
#define NPAIR 8192
#define D     128

#define NTILE 128                         // 16384 / 128
#define NTRI  (NTILE * (NTILE + 1) / 2)   // 8256 upper-tri tiles

__device__ __align__(16) uint8_t g_H8[(size_t)NROWS * D];   // e4m3
__device__ float g_rowsum[NROWS];
__device__ float g_pos[NPAIR];

__device__ __forceinline__ float ex2f(float x) {
    float y;
    asm("ex2.approx.ftz.f32 %0, %1;" : "=f"(y) : "f"(x));
    return y;
}

// pack 2 floats -> e4m3x2 (lo = second source operand)
__device__ __forceinline__ unsigned short fp8x2(float lo, float hi) {
    unsigned short q;
    asm("cvt.rn.satfinite.e4m3x2.f32 %0, %1, %2;" : "=h"(q) : "f"(hi), "f"(lo));
    return q;
}

// fp8 mma, f16 accumulators: c[0] = f16x2 {row g, cols 2tg,2tg+1},
// c[1] = f16x2 {row g+8, cols 2tg,2tg+1}
__device__ __forceinline__ void mma16832h(unsigned c[2], const unsigned a[4], const unsigned b[2]) {
    asm volatile(
        "mma.sync.aligned.m16n8k32.row.col.f16.e4m3.e4m3.f16 "
        "{%0,%1}, {%2,%3,%4,%5}, {%6,%7}, {%0,%1};"
        : "+r"(c[0]), "+r"(c[1])
        : "r"(a[0]), "r"(a[1]), "r"(a[2]), "r"(a[3]), "r"(b[0]), "r"(b[1]));
}

// ---------------------------------------------------------------------------
// K1: one warp per pair i. fp32 norms/dots, fp8 outputs.
// ---------------------------------------------------------------------------
__global__ void norm_kernel(const float* __restrict__ h1, const float* __restrict__ h2) {
    const int gwarp = (blockIdx.x * blockDim.x + threadIdx.x) >> 5;
    const int lane  = threadIdx.x & 31;
    if (gwarp >= NPAIR) return;

    const float4 a = reinterpret_cast<const float4*>(h1 + (size_t)gwarp * D)[lane];
    const float4 b = reinterpret_cast<const float4*>(h2 + (size_t)gwarp * D)[lane];

    float s11 = a.x * a.x + a.y * a.y + a.z * a.z + a.w * a.w;
    float s22 = b.x * b.x + b.y * b.y + b.z * b.z + b.w * b.w;
    float s12 = a.x * b.x + a.y * b.y + a.z * b.z + a.w * b.w;

    #pragma unroll
    for (int off = 16; off > 0; off >>= 1) {
        s11 += __shfl_xor_sync(0xffffffffu, s11, off);
        s22 += __shfl_xor_sync(0xffffffffu, s22, off);
        s12 += __shfl_xor_sync(0xffffffffu, s12, off);
    }

    const float i1 = rsqrtf(s11);
    const float i2 = rsqrtf(s22);

    const unsigned w1 = (unsigned)fp8x2(a.x * i1, a.y * i1) |
                        ((unsigned)fp8x2(a.z * i1, a.w * i1) << 16);
    const unsigned w2 = (unsigned)fp8x2(b.x * i2, b.y * i2) |
                        ((unsigned)fp8x2(b.z * i2, b.w * i2) << 16);

    reinterpret_cast<unsigned*>(g_H8 + (size_t)gwarp * D)[lane] = w1;
    reinterpret_cast<unsigned*>(g_H8 + (size_t)(gwarp + NPAIR) * D)[lane] = w2;

    if (lane == 0) {
        g_pos[gwarp] = s12 * i1 * i2;
        g_rowsum[gwarp] = 0.0f;
        g_rowsum[gwarp + NPAIR] = 0.0f;
    }
}

// ---------------------------------------------------------------------------
// K2: 256 threads (8 warps), warp grid 4x2, 32x64 warp tiles.
//
// SMEM layout: rows of 128 bytes, rotated by 16*row bytes (mod 128).
// Fragment accesses (4B at byte k0 + tg*4 (+16), row base+g) hit
// word tg + 4*g (mod 32): perfect bank bijection -> conflict-free.
// ---------------------------------------------------------------------------
__device__ __forceinline__ uint32_t rot_off(int row, int byte) {
    return (uint32_t)(row * 128 + ((byte + (row << 4)) & 127));
}

__global__ void __launch_bounds__(256, 2) gemm_kernel() {
    __shared__ __align__(16) uint8_t sA[128 * 128];
    __shared__ __align__(16) uint8_t sB[128 * 128];

    const int tid = threadIdx.x;

    // decode linear tile index p -> (bi, bj), bj >= bi
    const int p = blockIdx.x;
    int bi = (int)(128.5 - sqrt(128.5 * 128.5 - 2.0 * (double)p));
    if (bi > 0 && bi * (257 - bi) / 2 > p) --bi;
    if ((bi + 1) * (256 - bi) / 2 <= p) ++bi;
    const int bj = bi + (p - bi * (257 - bi) / 2);

    // load tiles: 128 rows x 8 chunks of 16B, rotated placement
    #pragma unroll
    for (int i = tid; i < 128 * 8; i += 256) {
        const int r = i >> 3, c = i & 7;
        const uint32_t dst = (uint32_t)(r * 128 + (((c + r) & 7) << 4));
        *reinterpret_cast<uint4*>(sA + dst) =
            *reinterpret_cast<const uint4*>(g_H8 + (size_t)(bi * 128 + r) * D + c * 16);
        *reinterpret_cast<uint4*>(sB + dst) =
            *reinterpret_cast<const uint4*>(g_H8 + (size_t)(bj * 128 + r) * D + c * 16);
    }
    __syncthreads();

    const int warp = tid >> 5;
    const int lane = tid & 31;
    const int wm = warp >> 1;       // 0..3  (32-row slice)
    const int wn = warp & 1;        // 0..1  (64-col slice)
    const int g  = lane >> 2;       // 0..7
    const int tg = lane & 3;        // 0..3

    unsigned acc[2][8][2];
    #pragma unroll
    for (int f = 0; f < 2; ++f)
        #pragma unroll
        for (int j = 0; j < 8; ++j) { acc[f][j][0] = 0u; acc[f][j][1] = 0u; }

    #pragma unroll
    for (int k = 0; k < 4; ++k) {       // K = 4 x 32
        const int k0 = k * 32 + tg * 4;
        unsigned a[2][4], b[8][2];
        #pragma unroll
        for (int f = 0; f < 2; ++f) {
            const int r0 = wm * 32 + f * 16 + g;
            const int r1 = r0 + 8;
            a[f][0] = *reinterpret_cast<const unsigned*>(sA + rot_off(r0, k0));
            a[f][1] = *reinterpret_cast<const unsigned*>(sA + rot_off(r1, k0));
            a[f][2] = *reinterpret_cast<const unsigned*>(sA + rot_off(r0, k0 + 16));
            a[f][3] = *reinterpret_cast<const unsigned*>(sA + rot_off(r1, k0 + 16));
        }
        #pragma unroll
        for (int j = 0; j < 8; ++j) {
            const int rn = wn * 64 + j * 8 + g;
            b[j][0] = *reinterpret_cast<const unsigned*>(sB + rot_off(rn, k0));
            b[j][1] = *reinterpret_cast<const unsigned*>(sB + rot_off(rn, k0 + 16));
        }
        #pragma unroll
        for (int f = 0; f < 2; ++f)
            #pragma unroll
            for (int j = 0; j < 8; ++j)
                mma16832h(acc[f][j], a[f], b[j]);
    }

    // Streaming epilogue: exp(2s) = 2^(KK*s); never materialize e[].
    // Per (f,j,q): q0=(g,2tg) q1=(g,2tg+1) q2=(g+8,2tg) q3=(g+8,2tg+1).
    const float KK = 2.8853900817779268f;
    const bool offdiag = (bj != bi);

    float rlo[2] = {0.0f, 0.0f}, rhi[2] = {0.0f, 0.0f};

    #pragma unroll
    for (int j = 0; j < 8; ++j) {
        float c0 = 0.0f, c1 = 0.0f;
        #pragma unroll
        for (int f = 0; f < 2; ++f) {
            const float2 lo = __half22float2(*reinterpret_cast<__half2*>(&acc[f][j][0]));
            const float2 hi = __half22float2(*reinterpret_cast<__half2*>(&acc[f][j][1]));
            const float e0 = ex2f(lo.x * KK);
            const float e1 = ex2f(lo.y * KK);
            const float e2 = ex2f(hi.x * KK);
            const float e3 = ex2f(hi.y * KK);
            rlo[f] += e0 + e1;
            rhi[f] += e2 + e3;
            c0 += e0 + e2;
            c1 += e1 + e3;
        }
        // column reduce over g-lanes, write col sums for this j
        if (offdiag) {
            c0 += __shfl_xor_sync(0xffffffffu, c0, 4);
            c0 += __shfl_xor_sync(0xffffffffu, c0, 8);
            c0 += __shfl_xor_sync(0xffffffffu, c0, 16);
            c1 += __shfl_xor_sync(0xffffffffu, c1, 4);
            c1 += __shfl_xor_sync(0xffffffffu, c1, 8);
            c1 += __shfl_xor_sync(0xffffffffu, c1, 16);
            if (g == 0) {
                const int col = bj * 128 + wn * 64 + j * 8 + 2 * tg;
                atomicAdd(&g_rowsum[col], c0);
                atomicAdd(&g_rowsum[col + 1], c1);
            }
        }
    }

    // row sums -> bi block (reduce over tg; both wn warps atomically combine)
    #pragma unroll
    for (int f = 0; f < 2; ++f) {
        float slo = rlo[f], shi = rhi[f];
        slo += __shfl_xor_sync(0xffffffffu, slo, 1);
        slo += __shfl_xor_sync(0xffffffffu, slo, 2);
        shi += __shfl_xor_sync(0xffffffffu, shi, 1);
        shi += __shfl_xor_sync(0xffffffffu, shi, 2);
        if (tg == 0) {
            const int row = bi * 128 + wm * 32 + f * 16 + g;
            atomicAdd(&g_rowsum[row], slo);
            atomicAdd(&g_rowsum[row + 8], shi);
        }
    }
}

// ---------------------------------------------------------------------------
// K3: loss = mean( log(rowsum_i - e^2) - 2 * pos[i mod NPAIR] )
// ---------------------------------------------------------------------------
__global__ void loss_kernel(float* __restrict__ out) {
    __shared__ float red[256];
    const float E2 = 7.389056098930650f;  // exp(1/t) = e^2
    float s = 0.0f;
    for (int i = threadIdx.x; i < NROWS; i += 256) {
        const float denom = g_rowsum[i] - E2;
        s += logf(denom) - 2.0f * g_pos[i & (NPAIR - 1)];
    }
    red[threadIdx.x] = s;
    __syncthreads();
    #pragma unroll
    for (int off = 128; off > 0; off >>= 1) {
        if (threadIdx.x < off) red[threadIdx.x] += red[threadIdx.x + off];
        __syncthreads();
    }
    if (threadIdx.x == 0) out[0] = red[0] * (1.0f / (float)NROWS);
}

extern "C" void kernel_launch(void* const* d_in, const int* in_sizes, int n_in,
                              void* d_out, int out_size) {
    const float* h1 = (const float*)d_in[0];
    const float* h2 = (const float*)d_in[1];

    norm_kernel<<<NPAIR / 8, 256>>>(h1, h2);
    gemm_kernel<<<NTRI, 256>>>();
    loss_kernel<<<1, 256>>>((float*)d_out);
}

// round 17
// speedup vs baseline: 1.2656x; 1.2656x over previous
#include <cuda_runtime.h>
#include <cuda_bf16.h>
#include <cuda_fp16.h>
#include <cuda_fp8.h>
#include <cstdint>
#include <stdint.h>
#include <math.h>

// NTXent loss, t = 0.5 — FP8 e4m3 mma, f16 accum, packed-f16 epilogue.
//
// K1: normalize rows, scale by sqrt(2*log2 e) so the mma accumulator holds
//     2*log2(e)*s directly; store e4m3. fp32 pos dots. zero rowsums.
// K2: one CTA per upper-triangular 128x128 tile of S' (4 warps, 64x64 tiles,
//     m16n8k32.f16.e4m3.e4m3.f16). Epilogue entirely in f16x2:
//     ex2.approx.f16x2 on accumulators, HADD2 row/col partials, packed shfl
//     butterflies; f32 only at the atomics. Row sums -> bi rows, col sums ->
//     bj rows (symmetry).
// K3: final log + mean reduction.
//
// Diagonal of exp(S/t) ~ e^2 (normalized rows); included in sums, subtracted.

#define NROWS 16384
#define NPAIR 8192
#define D     128

#define NTILE 128                         // 16384 / 128
#define NTRI  (NTILE * (NTILE + 1) / 2)   // 8256 upper-tri tiles

// sqrt(2*log2(e)) — folded exp scale
#define SQK 1.6986436f

__device__ __align__(16) uint8_t g_H8[(size_t)NROWS * D];   // e4m3, pre-scaled
__device__ float g_rowsum[NROWS];
__device__ float g_pos[NPAIR];

// pack 2 floats -> e4m3x2 (lo = second source operand)
__device__ __forceinline__ unsigned short fp8x2(float lo, float hi) {
    unsigned short q;
    asm("cvt.rn.satfinite.e4m3x2.f32 %0, %1, %2;" : "=h"(q) : "f"(hi), "f"(lo));
    return q;
}

// packed 2^x on f16x2
__device__ __forceinline__ unsigned h2ex2(unsigned x) {
    unsigned y;
    asm("ex2.approx.f16x2 %0, %1;" : "=r"(y) : "r"(x));
    return y;
}

__device__ __forceinline__ unsigned hadd2u(unsigned a, unsigned b) {
    unsigned y;
    asm("add.f16x2 %0, %1, %2;" : "=r"(y) : "r"(a), "r"(b));
    return y;
}

// fp8 mma, f16 accumulators: c[0] = f16x2 {row g, cols 2tg,2tg+1},
// c[1] = f16x2 {row g+8, cols 2tg,2tg+1}
__device__ __forceinline__ void mma16832h(unsigned c[2], const unsigned a[4], const unsigned b[2]) {
    asm volatile(
        "mma.sync.aligned.m16n8k32.row.col.f16.e4m3.e4m3.f16 "
        "{%0,%1}, {%2,%3,%4,%5}, {%6,%7}, {%0,%1};"
        : "+r"(c[0]), "+r"(c[1])
        : "r"(a[0]), "r"(a[1]), "r"(a[2]), "r"(a[3]), "r"(b[0]), "r"(b[1]));
}

// ---------------------------------------------------------------------------
// K1: one warp per pair i. fp32 norms/dots; outputs scaled by SQK.
// ---------------------------------------------------------------------------
__global__ void norm_kernel(const float* __restrict__ h1, const float* __restrict__ h2) {
    const int gwarp = (blockIdx.x * blockDim.x + threadIdx.x) >> 5;
    const int lane  = threadIdx.x & 31;
    if (gwarp >= NPAIR) return;

    const float4 a = reinterpret_cast<const float4*>(h1 + (size_t)gwarp * D)[lane];
    const float4 b = reinterpret_cast<const float4*>(h2 + (size_t)gwarp * D)[lane];

    float s11 = a.x * a.x + a.y * a.y + a.z * a.z + a.w * a.w;
    float s22 = b.x * b.x + b.y * b.y + b.z * b.z + b.w * b.w;
    float s12 = a.x * b.x + a.y * b.y + a.z * b.z + a.w * b.w;

    #pragma unroll
    for (int off = 16; off > 0; off >>= 1) {
        s11 += __shfl_xor_sync(0xffffffffu, s11, off);
        s22 += __shfl_xor_sync(0xffffffffu, s22, off);
        s12 += __shfl_xor_sync(0xffffffffu, s12, off);
    }

    const float i1 = rsqrtf(s11) * SQK;
    const float i2 = rsqrtf(s22) * SQK;

    const unsigned w1 = (unsigned)fp8x2(a.x * i1, a.y * i1) |
                        ((unsigned)fp8x2(a.z * i1, a.w * i1) << 16);
    const unsigned w2 = (unsigned)fp8x2(b.x * i2, b.y * i2) |
                        ((unsigned)fp8x2(b.z * i2, b.w * i2) << 16);

    reinterpret_cast<unsigned*>(g_H8 + (size_t)gwarp * D)[lane] = w1;
    reinterpret_cast<unsigned*>(g_H8 + (size_t)(gwarp + NPAIR) * D)[lane] = w2;

    if (lane == 0) {
        g_pos[gwarp] = s12 * rsqrtf(s11) * rsqrtf(s22);
        g_rowsum[gwarp] = 0.0f;
        g_rowsum[gwarp + NPAIR] = 0.0f;
    }
}

// ---------------------------------------------------------------------------
// K2: 128 threads (4 warps, 2x2), 64x64 warp tiles.
//
// SMEM layout: rows of 128 bytes, rotated by 16*row bytes (mod 128).
// Fragment accesses (4B at byte k0 + tg*4 (+16), row base+g) hit
// word tg + 4*g (mod 32): perfect bank bijection -> conflict-free.
// ---------------------------------------------------------------------------
__device__ __forceinline__ uint32_t rot_off(int row, int byte) {
    return (uint32_t)(row * 128 + ((byte + (row << 4)) & 127));
}

__global__ void __launch_bounds__(128, 4) gemm_kernel() {
    __shared__ __align__(16) uint8_t sA[128 * 128];
    __shared__ __align__(16) uint8_t sB[128 * 128];

    const int tid = threadIdx.x;

    // decode linear tile index p -> (bi, bj), bj >= bi
    const int p = blockIdx.x;
    int bi = (int)(128.5 - sqrt(128.5 * 128.5 - 2.0 * (double)p));
    if (bi > 0 && bi * (257 - bi) / 2 > p) --bi;
    if ((bi + 1) * (256 - bi) / 2 <= p) ++bi;
    const int bj = bi + (p - bi * (257 - bi) / 2);

    // load tiles: 128 rows x 8 chunks of 16B, rotated placement
    #pragma unroll
    for (int i = tid; i < 128 * 8; i += 128) {
        const int r = i >> 3, c = i & 7;
        const uint32_t dst = (uint32_t)(r * 128 + (((c + r) & 7) << 4));
        *reinterpret_cast<uint4*>(sA + dst) =
            *reinterpret_cast<const uint4*>(g_H8 + (size_t)(bi * 128 + r) * D + c * 16);
        *reinterpret_cast<uint4*>(sB + dst) =
            *reinterpret_cast<const uint4*>(g_H8 + (size_t)(bj * 128 + r) * D + c * 16);
    }
    __syncthreads();

    const int warp = tid >> 5;
    const int lane = tid & 31;
    const int wm = warp >> 1;       // 0..1
    const int wn = warp & 1;        // 0..1
    const int g  = lane >> 2;       // 0..7
    const int tg = lane & 3;        // 0..3

    unsigned acc[4][8][2];
    #pragma unroll
    for (int f = 0; f < 4; ++f)
        #pragma unroll
        for (int j = 0; j < 8; ++j) { acc[f][j][0] = 0u; acc[f][j][1] = 0u; }

    #pragma unroll
    for (int k = 0; k < 4; ++k) {       // K = 4 x 32
        const int k0 = k * 32 + tg * 4;
        unsigned a[4][4], b[8][2];
        #pragma unroll
        for (int f = 0; f < 4; ++f) {
            const int r0 = wm * 64 + f * 16 + g;
            const int r1 = r0 + 8;
            a[f][0] = *reinterpret_cast<const unsigned*>(sA + rot_off(r0, k0));
            a[f][1] = *reinterpret_cast<const unsigned*>(sA + rot_off(r1, k0));
            a[f][2] = *reinterpret_cast<const unsigned*>(sA + rot_off(r0, k0 + 16));
            a[f][3] = *reinterpret_cast<const unsigned*>(sA + rot_off(r1, k0 + 16));
        }
        #pragma unroll
        for (int j = 0; j < 8; ++j) {
            const int rn = wn * 64 + j * 8 + g;
            b[j][0] = *reinterpret_cast<const unsigned*>(sB + rot_off(rn, k0));
            b[j][1] = *reinterpret_cast<const unsigned*>(sB + rot_off(rn, k0 + 16));
        }
        #pragma unroll
        for (int f = 0; f < 4; ++f)
            #pragma unroll
            for (int j = 0; j < 8; ++j)
                mma16832h(acc[f][j], a[f], b[j]);
    }

    // ---- packed f16 epilogue ----
    // acc already holds 2*log2(e)*s -> exp(s/t) = ex2(acc).
    // rs0[f]: f16x2 {col-even, col-odd} partial of row (wm*64+f*16+g)
    // rs1[f]: same for row +8.  cj: packed col pair partial over 32 rows.
    const bool offdiag = (bj != bi);

    unsigned rs0[4] = {0u, 0u, 0u, 0u};
    unsigned rs1[4] = {0u, 0u, 0u, 0u};

    #pragma unroll
    for (int j = 0; j < 8; ++j) {
        unsigned cj = 0u;
        #pragma unroll
        for (int f = 0; f < 4; ++f) {
            const unsigned e0 = h2ex2(acc[f][j][0]);   // row g,   cols 2tg,2tg+1
            const unsigned e1 = h2ex2(acc[f][j][1]);   // row g+8, cols 2tg,2tg+1
            rs0[f] = hadd2u(rs0[f], e0);
            rs1[f] = hadd2u(rs1[f], e1);
            cj = hadd2u(cj, hadd2u(e0, e1));
        }
        if (offdiag) {
            cj = hadd2u(cj, __shfl_xor_sync(0xffffffffu, cj, 4));
            cj = hadd2u(cj, __shfl_xor_sync(0xffffffffu, cj, 8));
            cj = hadd2u(cj, __shfl_xor_sync(0xffffffffu, cj, 16));
            if (g == 0) {
                const __half2 h = *reinterpret_cast<const __half2*>(&cj);
                const int col = bj * 128 + wn * 64 + j * 8 + 2 * tg;
                atomicAdd(&g_rowsum[col], __low2float(h));
                atomicAdd(&g_rowsum[col + 1], __high2float(h));
            }
        }
    }

    // row sums -> bi block (f32 from here; reduce over tg lanes)
    #pragma unroll
    for (int f = 0; f < 4; ++f) {
        const __half2 h0 = *reinterpret_cast<const __half2*>(&rs0[f]);
        const __half2 h1 = *reinterpret_cast<const __half2*>(&rs1[f]);
        float slo = __low2float(h0) + __high2float(h0);
        float shi = __low2float(h1) + __high2float(h1);
        slo += __shfl_xor_sync(0xffffffffu, slo, 1);
        slo += __shfl_xor_sync(0xffffffffu, slo, 2);
        shi += __shfl_xor_sync(0xffffffffu, shi, 1);
        shi += __shfl_xor_sync(0xffffffffu, shi, 2);
        if (tg == 0) {
            const int row = bi * 128 + wm * 64 + f * 16 + g;
            atomicAdd(&g_rowsum[row], slo);
            atomicAdd(&g_rowsum[row + 8], shi);
        }
    }
}

// ---------------------------------------------------------------------------
// K3: loss = mean( log(rowsum_i - e^2) - 2 * pos[i mod NPAIR] )
// ---------------------------------------------------------------------------
__global__ void loss_kernel(float* __restrict__ out) {
    __shared__ float red[256];
    const float E2 = 7.389056098930650f;  // exp(1/t) = e^2
    float s = 0.0f;
    for (int i = threadIdx.x; i < NROWS; i += 256) {
        const float denom = g_rowsum[i] - E2;
        s += logf(denom) - 2.0f * g_pos[i & (NPAIR - 1)];
    }
    red[threadIdx.x] = s;
    __syncthreads();
    #pragma unroll
    for (int off = 128; off > 0; off >>= 1) {
        if (threadIdx.x < off) red[threadIdx.x] += red[threadIdx.x + off];
        __syncthreads();
    }
    if (threadIdx.x == 0) out[0] = red[0] * (1.0f / (float)NROWS);
}

extern "C" void kernel_launch(void* const* d_in, const int* in_sizes, int n_in,
                              void* d_out, int out_size) {
    const float* h1 = (const float*)d_in[0];
    const float* h2 = (const float*)d_in[1];

    norm_kernel<<<NPAIR / 8, 256>>>(h1, h2);
    gemm_kernel<<<NTRI, 128>>>();
    loss_kernel<<<1, 256>>>((float*)d_out);
}